// round 13
// baseline (speedup 1.0000x reference)
#include <cuda_runtime.h>
#include <cstdint>

#define HH 64
#define NN 512
#define BB 128

__device__ float g_qp[BB * NN * HH];
__device__ float g_kp[BB * NN * HH];
__device__ float g_vp[BB * NN * HH];

// ---------------- helpers ----------------
__device__ __forceinline__ uint32_t tf32r(float f) {
    uint32_t u;
    asm("cvt.rna.tf32.f32 %0, %1;" : "=r"(u) : "f"(f));
    return u;
}
__device__ __forceinline__ void mma_tf32(float* d, const uint32_t* a,
                                         uint32_t b0, uint32_t b1) {
    asm volatile(
        "mma.sync.aligned.m16n8k8.row.col.f32.tf32.tf32.f32 "
        "{%0,%1,%2,%3}, {%4,%5,%6,%7}, {%8,%9}, {%0,%1,%2,%3};"
        : "+f"(d[0]), "+f"(d[1]), "+f"(d[2]), "+f"(d[3])
        : "r"(a[0]), "r"(a[1]), "r"(a[2]), "r"(a[3]), "r"(b0), "r"(b1));
}

// exp(s * 0.125) on FMA/ALU pipes only.
__device__ __forceinline__ float fexp8(float s) {
    float y = s * 0.18033688011112042f;      // 0.125 * log2(e)
    float z = y + 12582912.0f;               // RN to integer
    int   i = __float_as_int(z) - 0x4B400000;
    float f = y - (z - 12582912.0f);
    float p = 0.0013333558f;
    p = p * f + 0.0096181291f;
    p = p * f + 0.0555041087f;
    p = p * f + 0.2402265070f;
    p = p * f + 0.6931471806f;
    p = p * f + 1.0f;
    return __int_as_float(__float_as_int(p) + (i << 23));
}

// ---------------------------------------------------------------------------
// Per-batch projection: CTA = one (batch, q/k/v), all 512 rows in 4 sub-tiles.
// dst[b,n,h] = x[n,b,:] . W[h,:] + bias[h], stored tf32-pre-rounded.
// ---------------------------------------------------------------------------
__global__ __launch_bounds__(256, 2) void proj_kernel(
    int b0,
    const float* __restrict__ q, const float* __restrict__ k,
    const float* __restrict__ v,
    const float* __restrict__ Wq, const float* __restrict__ bq,
    const float* __restrict__ Wk, const float* __restrict__ bk,
    const float* __restrict__ Wv, const float* __restrict__ bv)
{
    __shared__ uint32_t sX[128 * 68];
    __shared__ uint32_t sW[64 * 68];
    __shared__ float    sB[64];

    const int b = b0 + blockIdx.x;

    const float* x; const float* W; const float* bias; float* dst;
    if (blockIdx.y == 0)      { x = q; W = Wq; bias = bq; dst = g_qp; }
    else if (blockIdx.y == 1) { x = k; W = Wk; bias = bk; dst = g_kp; }
    else                      { x = v; W = Wv; bias = bv; dst = g_vp; }

    const int tid = threadIdx.x;

    // Load W (64x64, tf32-rounded) and bias once
    #pragma unroll
    for (int it = 0; it < 4; it++) {
        int idx = tid + it * 256;
        int r = idx >> 4, c4 = idx & 15;
        float4 t = *reinterpret_cast<const float4*>(W + (size_t)r * HH + c4 * 4);
        uint4 u = { tf32r(t.x), tf32r(t.y), tf32r(t.z), tf32r(t.w) };
        *reinterpret_cast<uint4*>(&sW[r * 68 + c4 * 4]) = u;
    }
    if (tid < 64) sB[tid] = bias[tid];

    const int w    = tid >> 5;
    const int lane = tid & 31;
    const int lx   = lane & 3;
    const int ly   = lane >> 2;
    const int r0   = w * 16 + ly;
    const int r1   = r0 + 8;

    for (int sub = 0; sub < 4; sub++) {
        const int nb = sub * 128;
        __syncthreads();   // sX free (and W ready on first iter)

        // Load X tile: 128 rows (n = nb..nb+127) of batch b, tf32-rounded
        #pragma unroll
        for (int it = 0; it < 8; it++) {
            int idx = tid + it * 256;
            int r = idx >> 4, c4 = idx & 15;
            float4 t = *reinterpret_cast<const float4*>(
                x + ((size_t)(nb + r) * BB + b) * HH + c4 * 4);
            uint4 u = { tf32r(t.x), tf32r(t.y), tf32r(t.z), tf32r(t.w) };
            *reinterpret_cast<uint4*>(&sX[r * 68 + c4 * 4]) = u;
        }
        __syncthreads();

        float acc[8][4];
        #pragma unroll
        for (int t = 0; t < 8; t++)
            #pragma unroll
            for (int i = 0; i < 4; i++) acc[t][i] = 0.f;

        #pragma unroll
        for (int k0 = 0; k0 < 64; k0 += 8) {
            uint32_t a[4];
            a[0] = sX[r0 * 68 + k0 + lx];
            a[1] = sX[r1 * 68 + k0 + lx];
            a[2] = sX[r0 * 68 + k0 + lx + 4];
            a[3] = sX[r1 * 68 + k0 + lx + 4];
            #pragma unroll
            for (int t = 0; t < 8; t++) {
                uint32_t bw0 = sW[(t * 8 + ly) * 68 + k0 + lx];
                uint32_t bw1 = sW[(t * 8 + ly) * 68 + k0 + 4 + lx];
                mma_tf32(acc[t], a, bw0, bw1);
            }
        }

        float* orow0 = dst + ((size_t)b * NN + nb + r0) * HH;
        float* orow1 = dst + ((size_t)b * NN + nb + r1) * HH;
        #pragma unroll
        for (int t = 0; t < 8; t++) {
            int c0 = t * 8 + 2 * lx;
            float bb0 = sB[c0], bb1 = sB[c0 + 1];
            float2 o0 = make_float2(__uint_as_float(tf32r(acc[t][0] + bb0)),
                                    __uint_as_float(tf32r(acc[t][1] + bb1)));
            float2 o1 = make_float2(__uint_as_float(tf32r(acc[t][2] + bb0)),
                                    __uint_as_float(tf32r(acc[t][3] + bb1)));
            *reinterpret_cast<float2*>(orow0 + c0) = o0;
            *reinterpret_cast<float2*>(orow1 + c0) = o1;
        }
    }
}

// ---------------------------------------------------------------------------
// Attention (R8 version): CTA = 64 n-rows x one batch, 512 threads (16 warps
// = 4 row-stripes x 4 col-quads), 4 chunks of 128 keys, e-tile in smem.
// ---------------------------------------------------------------------------
// smem float offsets
#define OQ   0                      // 64 x 68
#define OK_  4352                   // 128 x 68
#define OV   13056                  // 128 x 72
#define OA   22272                  // 64 x 516
#define OS   55296                  // 256 partial row sums
#define OI   55552                  // 64 inverse sums
#define SMEM_FLOATS 55616

__global__ __launch_bounds__(512, 1) void attn_kernel(
    int b0,
    const float* __restrict__ mask,
    float* __restrict__ out,     // [N,B,H]
    float* __restrict__ Aout)    // [B,N,N]
{
    extern __shared__ float sm[];
    float*    sAf = sm + OA;
    uint32_t* sQu = reinterpret_cast<uint32_t*>(sm + OQ);
    uint32_t* sKu = reinterpret_cast<uint32_t*>(sm + OK_);
    uint32_t* sVu = reinterpret_cast<uint32_t*>(sm + OV);
    uint32_t* sAu = reinterpret_cast<uint32_t*>(sm + OA);

    const int tid  = threadIdx.x;
    const int w    = tid >> 5;
    const int lane = tid & 31;
    const int lx   = lane & 3;
    const int ly   = lane >> 2;
    const int stripe = w & 3;
    const int quad   = w >> 2;
    const int r0 = stripe * 16 + ly, r1 = r0 + 8;

    const int n0 = blockIdx.x * 64;
    const int b  = b0 + blockIdx.y;

    const float* qp = g_qp + (size_t)b * NN * HH;
    const float* kp = g_kp + (size_t)b * NN * HH;
    const float* vp = g_vp + (size_t)b * NN * HH;
    const float* mbase = mask + ((size_t)b * NN + n0) * NN;

    #pragma unroll
    for (int it = 0; it < 2; it++) {
        int idx = tid + it * 512;
        int r = idx >> 4, c4 = idx & 15;
        float4 t = *reinterpret_cast<const float4*>(qp + (size_t)(n0 + r) * HH + c4 * 4);
        *reinterpret_cast<float4*>(&sm[OQ + r * 68 + c4 * 4]) = t;
    }
    __syncthreads();

    uint32_t qf[8][4];
    #pragma unroll
    for (int kk = 0; kk < 8; kk++) {
        int k0 = kk * 8;
        qf[kk][0] = sQu[r0 * 68 + k0 + lx];
        qf[kk][1] = sQu[r1 * 68 + k0 + lx];
        qf[kk][2] = sQu[r0 * 68 + k0 + lx + 4];
        qf[kk][3] = sQu[r1 * 68 + k0 + lx + 4];
    }

    float oacc[2][4];
    #pragma unroll
    for (int t = 0; t < 2; t++)
        #pragma unroll
        for (int i = 0; i < 4; i++) oacc[t][i] = 0.f;
    float rsum0 = 0.f, rsum1 = 0.f;

    for (int c = 0; c < 4; c++) {
        const int mt = c * 128;
        __syncthreads();

        #pragma unroll
        for (int it = 0; it < 4; it++) {
            int idx = tid + it * 512;
            int r = idx >> 4, c4 = idx & 15;
            float4 t = *reinterpret_cast<const float4*>(kp + (size_t)(mt + r) * HH + c4 * 4);
            *reinterpret_cast<float4*>(&sm[OK_ + r * 68 + c4 * 4]) = t;
            float4 s = *reinterpret_cast<const float4*>(vp + (size_t)(mt + r) * HH + c4 * 4);
            *reinterpret_cast<float4*>(&sm[OV + r * 72 + c4 * 4]) = s;
        }
        __syncthreads();

        float2 m0[4], m1[4];
        #pragma unroll
        for (int t = 0; t < 4; t++) {
            int gc = mt + quad * 32 + t * 8 + 2 * lx;
            m0[t] = *reinterpret_cast<const float2*>(mbase + (size_t)r0 * NN + gc);
            m1[t] = *reinterpret_cast<const float2*>(mbase + (size_t)r1 * NN + gc);
        }

        float sacc[4][4];
        #pragma unroll
        for (int t = 0; t < 4; t++)
            #pragma unroll
            for (int i = 0; i < 4; i++) sacc[t][i] = 0.f;

        #pragma unroll
        for (int kk = 0; kk < 8; kk++) {
            int k0 = kk * 8;
            #pragma unroll
            for (int t = 0; t < 4; t++) {
                int key = quad * 32 + t * 8 + ly;
                uint32_t bk0 = sKu[key * 68 + k0 + lx];
                uint32_t bk1 = sKu[key * 68 + k0 + 4 + lx];
                mma_tf32(sacc[t], qf[kk], bk0, bk1);
            }
        }

        #pragma unroll
        for (int t = 0; t < 4; t++) {
            int gc = mt + quad * 32 + t * 8 + 2 * lx;
            float e00 = __uint_as_float(tf32r(fexp8(sacc[t][0]) * m0[t].x));
            float e01 = __uint_as_float(tf32r(fexp8(sacc[t][1]) * m0[t].y));
            float e10 = __uint_as_float(tf32r(fexp8(sacc[t][2]) * m1[t].x));
            float e11 = __uint_as_float(tf32r(fexp8(sacc[t][3]) * m1[t].y));
            rsum0 += e00 + e01;
            rsum1 += e10 + e11;
            *reinterpret_cast<float2*>(&sAf[r0 * 516 + gc]) = make_float2(e00, e01);
            *reinterpret_cast<float2*>(&sAf[r1 * 516 + gc]) = make_float2(e10, e11);
        }
        __syncthreads();

        #pragma unroll
        for (int k0 = 0; k0 < 128; k0 += 8) {
            uint32_t a[4];
            a[0] = sAu[r0 * 516 + mt + k0 + lx];
            a[1] = sAu[r1 * 516 + mt + k0 + lx];
            a[2] = sAu[r0 * 516 + mt + k0 + lx + 4];
            a[3] = sAu[r1 * 516 + mt + k0 + lx + 4];
            #pragma unroll
            for (int t = 0; t < 2; t++) {
                int h = quad * 16 + t * 8 + ly;
                uint32_t bv0 = sVu[(k0 + lx) * 72 + h];
                uint32_t bv1 = sVu[(k0 + 4 + lx) * 72 + h];
                mma_tf32(oacc[t], a, bv0, bv1);
            }
        }
    }

    rsum0 += __shfl_xor_sync(0xffffffff, rsum0, 1);
    rsum0 += __shfl_xor_sync(0xffffffff, rsum0, 2);
    rsum1 += __shfl_xor_sync(0xffffffff, rsum1, 1);
    rsum1 += __shfl_xor_sync(0xffffffff, rsum1, 2);
    if (lx == 0) {
        sm[OS + quad * 64 + r0] = rsum0;
        sm[OS + quad * 64 + r1] = rsum1;
    }
    __syncthreads();
    if (tid < 64) {
        float s = sm[OS + tid] + sm[OS + 64 + tid] + sm[OS + 128 + tid] + sm[OS + 192 + tid];
        sm[OI + tid] = (s == 0.f) ? 1.f : (1.f / s);
    }
    __syncthreads();

    {
        int row = tid >> 3, s8 = tid & 7;
        float inv = sm[OI + row];
        float4* grow = reinterpret_cast<float4*>(Aout + ((size_t)b * NN + n0 + row) * NN);
        #pragma unroll
        for (int i = 0; i < 16; i++) {
            int c4 = s8 + 8 * i;
            float4 t = *reinterpret_cast<const float4*>(&sAf[row * 516 + 4 * c4]);
            t.x *= inv; t.y *= inv; t.z *= inv; t.w *= inv;
            grow[c4] = t;
        }
    }

    {
        float* sO = sm + OK_;
        float i0 = sm[OI + r0], i1 = sm[OI + r1];
        #pragma unroll
        for (int t = 0; t < 2; t++) {
            int h = quad * 16 + t * 8 + 2 * lx;
            *reinterpret_cast<float2*>(&sO[r0 * 68 + h]) =
                make_float2(oacc[t][0] * i0, oacc[t][1] * i0);
            *reinterpret_cast<float2*>(&sO[r1 * 68 + h]) =
                make_float2(oacc[t][2] * i1, oacc[t][3] * i1);
        }
        __syncthreads();
        #pragma unroll
        for (int it = 0; it < 2; it++) {
            int idx = tid + it * 512;
            int row = idx >> 4, c4 = idx & 15;
            float4 t = *reinterpret_cast<const float4*>(&sO[row * 68 + 4 * c4]);
            *reinterpret_cast<float4*>(out + ((size_t)(n0 + row) * BB + b) * HH + 4 * c4) = t;
        }
    }
}

// ---------------------------------------------------------------------------
// Stream pool created at static init (host-side objects only; no device mem).
// ---------------------------------------------------------------------------
#define NGROUPS 8
struct Orch {
    cudaStream_t s[NGROUPS];
    cudaEvent_t  e0;
    cudaEvent_t  eg[NGROUPS];
    Orch() {
        for (int i = 0; i < NGROUPS; i++)
            cudaStreamCreateWithFlags(&s[i], cudaStreamNonBlocking);
        cudaEventCreateWithFlags(&e0, cudaEventDisableTiming);
        for (int i = 0; i < NGROUPS; i++)
            cudaEventCreateWithFlags(&eg[i], cudaEventDisableTiming);
    }
};
static Orch g_orch;

extern "C" void kernel_launch(void* const* d_in, const int* in_sizes, int n_in,
                              void* d_out, int out_size)
{
    const float* q    = (const float*)d_in[0];
    const float* k    = (const float*)d_in[1];
    const float* v    = (const float*)d_in[2];
    const float* mask = (const float*)d_in[3];
    const float* Wq   = (const float*)d_in[4];
    const float* bq   = (const float*)d_in[5];
    const float* Wk   = (const float*)d_in[6];
    const float* bk   = (const float*)d_in[7];
    const float* Wv   = (const float*)d_in[8];
    const float* bv   = (const float*)d_in[9];

    float* out  = (float*)d_out;                         // [N,B,H] first
    float* Aout = (float*)d_out + (size_t)NN * BB * HH;  // then [B,N,N]

    const int smem_bytes = SMEM_FLOATS * 4;
    cudaFuncSetAttribute(attn_kernel, cudaFuncAttributeMaxDynamicSharedMemorySize,
                         smem_bytes);

    const int BPG = BB / NGROUPS;    // batches per group (16)

    // fork
    cudaEventRecord(g_orch.e0, (cudaStream_t)0);
    for (int g = 0; g < NGROUPS; g++) {
        cudaStreamWaitEvent(g_orch.s[g], g_orch.e0, 0);
        proj_kernel<<<dim3(BPG, 3), 256, 0, g_orch.s[g]>>>(
            g * BPG, q, k, v, Wq, bq, Wk, bk, Wv, bv);
        attn_kernel<<<dim3(NN / 64, BPG), 512, smem_bytes, g_orch.s[g]>>>(
            g * BPG, mask, out, Aout);
        cudaEventRecord(g_orch.eg[g], g_orch.s[g]);
    }
    // join
    for (int g = 0; g < NGROUPS; g++)
        cudaStreamWaitEvent((cudaStream_t)0, g_orch.eg[g], 0);
}

// round 14
// speedup vs baseline: 1.0255x; 1.0255x over previous
#include <cuda_runtime.h>
#include <cstdint>

#define HH 64
#define NN 512
#define BB 128

__device__ float g_qp[BB * NN * HH];
__device__ float g_kp[BB * NN * HH];
__device__ float g_vp[BB * NN * HH];

// ---------------- helpers ----------------
__device__ __forceinline__ uint32_t tf32r(float f) {
    uint32_t u;
    asm("cvt.rna.tf32.f32 %0, %1;" : "=r"(u) : "f"(f));
    return u;
}
__device__ __forceinline__ void mma_tf32(float* d, const uint32_t* a,
                                         uint32_t b0, uint32_t b1) {
    asm volatile(
        "mma.sync.aligned.m16n8k8.row.col.f32.tf32.tf32.f32 "
        "{%0,%1,%2,%3}, {%4,%5,%6,%7}, {%8,%9}, {%0,%1,%2,%3};"
        : "+f"(d[0]), "+f"(d[1]), "+f"(d[2]), "+f"(d[3])
        : "r"(a[0]), "r"(a[1]), "r"(a[2]), "r"(a[3]), "r"(b0), "r"(b1));
}

// exp(s * 0.125) on FMA/ALU pipes only.
__device__ __forceinline__ float fexp8(float s) {
    float y = s * 0.18033688011112042f;      // 0.125 * log2(e)
    float z = y + 12582912.0f;               // RN to integer
    int   i = __float_as_int(z) - 0x4B400000;
    float f = y - (z - 12582912.0f);
    float p = 0.0013333558f;
    p = p * f + 0.0096181291f;
    p = p * f + 0.0555041087f;
    p = p * f + 0.2402265070f;
    p = p * f + 0.6931471806f;
    p = p * f + 1.0f;
    return __int_as_float(__float_as_int(p) + (i << 23));
}

// ---------------------------------------------------------------------------
// Per-batch projection: CTA = one (batch, q/k/v), all 512 rows in 4 sub-tiles.
// dst[b,n,h] = x[n,b,:] . W[h,:] + bias[h], stored tf32-pre-rounded.
// ---------------------------------------------------------------------------
__global__ __launch_bounds__(256, 2) void proj_kernel(
    int b0,
    const float* __restrict__ q, const float* __restrict__ k,
    const float* __restrict__ v,
    const float* __restrict__ Wq, const float* __restrict__ bq,
    const float* __restrict__ Wk, const float* __restrict__ bk,
    const float* __restrict__ Wv, const float* __restrict__ bv)
{
    __shared__ uint32_t sX[128 * 68];
    __shared__ uint32_t sW[64 * 68];
    __shared__ float    sB[64];

    const int b = b0 + blockIdx.x;

    const float* x; const float* W; const float* bias; float* dst;
    if (blockIdx.y == 0)      { x = q; W = Wq; bias = bq; dst = g_qp; }
    else if (blockIdx.y == 1) { x = k; W = Wk; bias = bk; dst = g_kp; }
    else                      { x = v; W = Wv; bias = bv; dst = g_vp; }

    const int tid = threadIdx.x;

    #pragma unroll
    for (int it = 0; it < 4; it++) {
        int idx = tid + it * 256;
        int r = idx >> 4, c4 = idx & 15;
        float4 t = *reinterpret_cast<const float4*>(W + (size_t)r * HH + c4 * 4);
        uint4 u = { tf32r(t.x), tf32r(t.y), tf32r(t.z), tf32r(t.w) };
        *reinterpret_cast<uint4*>(&sW[r * 68 + c4 * 4]) = u;
    }
    if (tid < 64) sB[tid] = bias[tid];

    const int w    = tid >> 5;
    const int lane = tid & 31;
    const int lx   = lane & 3;
    const int ly   = lane >> 2;
    const int r0   = w * 16 + ly;
    const int r1   = r0 + 8;

    for (int sub = 0; sub < 4; sub++) {
        const int nb = sub * 128;
        __syncthreads();   // sX free (and W ready on first iter)

        #pragma unroll
        for (int it = 0; it < 8; it++) {
            int idx = tid + it * 256;
            int r = idx >> 4, c4 = idx & 15;
            float4 t = *reinterpret_cast<const float4*>(
                x + ((size_t)(nb + r) * BB + b) * HH + c4 * 4);
            uint4 u = { tf32r(t.x), tf32r(t.y), tf32r(t.z), tf32r(t.w) };
            *reinterpret_cast<uint4*>(&sX[r * 68 + c4 * 4]) = u;
        }
        __syncthreads();

        float acc[8][4];
        #pragma unroll
        for (int t = 0; t < 8; t++)
            #pragma unroll
            for (int i = 0; i < 4; i++) acc[t][i] = 0.f;

        #pragma unroll
        for (int k0 = 0; k0 < 64; k0 += 8) {
            uint32_t a[4];
            a[0] = sX[r0 * 68 + k0 + lx];
            a[1] = sX[r1 * 68 + k0 + lx];
            a[2] = sX[r0 * 68 + k0 + lx + 4];
            a[3] = sX[r1 * 68 + k0 + lx + 4];
            #pragma unroll
            for (int t = 0; t < 8; t++) {
                uint32_t bw0 = sW[(t * 8 + ly) * 68 + k0 + lx];
                uint32_t bw1 = sW[(t * 8 + ly) * 68 + k0 + 4 + lx];
                mma_tf32(acc[t], a, bw0, bw1);
            }
        }

        float* orow0 = dst + ((size_t)b * NN + nb + r0) * HH;
        float* orow1 = dst + ((size_t)b * NN + nb + r1) * HH;
        #pragma unroll
        for (int t = 0; t < 8; t++) {
            int c0 = t * 8 + 2 * lx;
            float bb0 = sB[c0], bb1 = sB[c0 + 1];
            float2 o0 = make_float2(__uint_as_float(tf32r(acc[t][0] + bb0)),
                                    __uint_as_float(tf32r(acc[t][1] + bb1)));
            float2 o1 = make_float2(__uint_as_float(tf32r(acc[t][2] + bb0)),
                                    __uint_as_float(tf32r(acc[t][3] + bb1)));
            *reinterpret_cast<float2*>(orow0 + c0) = o0;
            *reinterpret_cast<float2*>(orow1 + c0) = o1;
        }
    }
}

// ---------------------------------------------------------------------------
// Attention (R8 version): CTA = 64 n-rows x one batch, 512 threads (16 warps
// = 4 row-stripes x 4 col-quads), 4 chunks of 128 keys, e-tile in smem.
// ---------------------------------------------------------------------------
// smem float offsets
#define OQ   0                      // 64 x 68
#define OK_  4352                   // 128 x 68
#define OV   13056                  // 128 x 72
#define OA   22272                  // 64 x 516
#define OS   55296                  // 256 partial row sums
#define OI   55552                  // 64 inverse sums
#define SMEM_FLOATS 55616

__global__ __launch_bounds__(512, 1) void attn_kernel(
    int b0,
    const float* __restrict__ mask,
    float* __restrict__ out,     // [N,B,H]
    float* __restrict__ Aout)    // [B,N,N]
{
    extern __shared__ float sm[];
    float*    sAf = sm + OA;
    uint32_t* sQu = reinterpret_cast<uint32_t*>(sm + OQ);
    uint32_t* sKu = reinterpret_cast<uint32_t*>(sm + OK_);
    uint32_t* sVu = reinterpret_cast<uint32_t*>(sm + OV);
    uint32_t* sAu = reinterpret_cast<uint32_t*>(sm + OA);

    const int tid  = threadIdx.x;
    const int w    = tid >> 5;
    const int lane = tid & 31;
    const int lx   = lane & 3;
    const int ly   = lane >> 2;
    const int stripe = w & 3;
    const int quad   = w >> 2;
    const int r0 = stripe * 16 + ly, r1 = r0 + 8;

    const int n0 = blockIdx.x * 64;
    const int b  = b0 + blockIdx.y;

    const float* qp = g_qp + (size_t)b * NN * HH;
    const float* kp = g_kp + (size_t)b * NN * HH;
    const float* vp = g_vp + (size_t)b * NN * HH;
    const float* mbase = mask + ((size_t)b * NN + n0) * NN;

    #pragma unroll
    for (int it = 0; it < 2; it++) {
        int idx = tid + it * 512;
        int r = idx >> 4, c4 = idx & 15;
        float4 t = *reinterpret_cast<const float4*>(qp + (size_t)(n0 + r) * HH + c4 * 4);
        *reinterpret_cast<float4*>(&sm[OQ + r * 68 + c4 * 4]) = t;
    }
    __syncthreads();

    uint32_t qf[8][4];
    #pragma unroll
    for (int kk = 0; kk < 8; kk++) {
        int k0 = kk * 8;
        qf[kk][0] = sQu[r0 * 68 + k0 + lx];
        qf[kk][1] = sQu[r1 * 68 + k0 + lx];
        qf[kk][2] = sQu[r0 * 68 + k0 + lx + 4];
        qf[kk][3] = sQu[r1 * 68 + k0 + lx + 4];
    }

    float oacc[2][4];
    #pragma unroll
    for (int t = 0; t < 2; t++)
        #pragma unroll
        for (int i = 0; i < 4; i++) oacc[t][i] = 0.f;
    float rsum0 = 0.f, rsum1 = 0.f;

    for (int c = 0; c < 4; c++) {
        const int mt = c * 128;
        __syncthreads();

        #pragma unroll
        for (int it = 0; it < 4; it++) {
            int idx = tid + it * 512;
            int r = idx >> 4, c4 = idx & 15;
            float4 t = *reinterpret_cast<const float4*>(kp + (size_t)(mt + r) * HH + c4 * 4);
            *reinterpret_cast<float4*>(&sm[OK_ + r * 68 + c4 * 4]) = t;
            float4 s = *reinterpret_cast<const float4*>(vp + (size_t)(mt + r) * HH + c4 * 4);
            *reinterpret_cast<float4*>(&sm[OV + r * 72 + c4 * 4]) = s;
        }
        __syncthreads();

        float2 m0[4], m1[4];
        #pragma unroll
        for (int t = 0; t < 4; t++) {
            int gc = mt + quad * 32 + t * 8 + 2 * lx;
            m0[t] = *reinterpret_cast<const float2*>(mbase + (size_t)r0 * NN + gc);
            m1[t] = *reinterpret_cast<const float2*>(mbase + (size_t)r1 * NN + gc);
        }

        float sacc[4][4];
        #pragma unroll
        for (int t = 0; t < 4; t++)
            #pragma unroll
            for (int i = 0; i < 4; i++) sacc[t][i] = 0.f;

        #pragma unroll
        for (int kk = 0; kk < 8; kk++) {
            int k0 = kk * 8;
            #pragma unroll
            for (int t = 0; t < 4; t++) {
                int key = quad * 32 + t * 8 + ly;
                uint32_t bk0 = sKu[key * 68 + k0 + lx];
                uint32_t bk1 = sKu[key * 68 + k0 + 4 + lx];
                mma_tf32(sacc[t], qf[kk], bk0, bk1);
            }
        }

        #pragma unroll
        for (int t = 0; t < 4; t++) {
            int gc = mt + quad * 32 + t * 8 + 2 * lx;
            float e00 = __uint_as_float(tf32r(fexp8(sacc[t][0]) * m0[t].x));
            float e01 = __uint_as_float(tf32r(fexp8(sacc[t][1]) * m0[t].y));
            float e10 = __uint_as_float(tf32r(fexp8(sacc[t][2]) * m1[t].x));
            float e11 = __uint_as_float(tf32r(fexp8(sacc[t][3]) * m1[t].y));
            rsum0 += e00 + e01;
            rsum1 += e10 + e11;
            *reinterpret_cast<float2*>(&sAf[r0 * 516 + gc]) = make_float2(e00, e01);
            *reinterpret_cast<float2*>(&sAf[r1 * 516 + gc]) = make_float2(e10, e11);
        }
        __syncthreads();

        #pragma unroll
        for (int k0 = 0; k0 < 128; k0 += 8) {
            uint32_t a[4];
            a[0] = sAu[r0 * 516 + mt + k0 + lx];
            a[1] = sAu[r1 * 516 + mt + k0 + lx];
            a[2] = sAu[r0 * 516 + mt + k0 + lx + 4];
            a[3] = sAu[r1 * 516 + mt + k0 + lx + 4];
            #pragma unroll
            for (int t = 0; t < 2; t++) {
                int h = quad * 16 + t * 8 + ly;
                uint32_t bv0 = sVu[(k0 + lx) * 72 + h];
                uint32_t bv1 = sVu[(k0 + 4 + lx) * 72 + h];
                mma_tf32(oacc[t], a, bv0, bv1);
            }
        }
    }

    rsum0 += __shfl_xor_sync(0xffffffff, rsum0, 1);
    rsum0 += __shfl_xor_sync(0xffffffff, rsum0, 2);
    rsum1 += __shfl_xor_sync(0xffffffff, rsum1, 1);
    rsum1 += __shfl_xor_sync(0xffffffff, rsum1, 2);
    if (lx == 0) {
        sm[OS + quad * 64 + r0] = rsum0;
        sm[OS + quad * 64 + r1] = rsum1;
    }
    __syncthreads();
    if (tid < 64) {
        float s = sm[OS + tid] + sm[OS + 64 + tid] + sm[OS + 128 + tid] + sm[OS + 192 + tid];
        sm[OI + tid] = (s == 0.f) ? 1.f : (1.f / s);
    }
    __syncthreads();

    {
        int row = tid >> 3, s8 = tid & 7;
        float inv = sm[OI + row];
        float4* grow = reinterpret_cast<float4*>(Aout + ((size_t)b * NN + n0 + row) * NN);
        #pragma unroll
        for (int i = 0; i < 16; i++) {
            int c4 = s8 + 8 * i;
            float4 t = *reinterpret_cast<const float4*>(&sAf[row * 516 + 4 * c4]);
            t.x *= inv; t.y *= inv; t.z *= inv; t.w *= inv;
            grow[c4] = t;
        }
    }

    {
        float* sO = sm + OK_;
        float i0 = sm[OI + r0], i1 = sm[OI + r1];
        #pragma unroll
        for (int t = 0; t < 2; t++) {
            int h = quad * 16 + t * 8 + 2 * lx;
            *reinterpret_cast<float2*>(&sO[r0 * 68 + h]) =
                make_float2(oacc[t][0] * i0, oacc[t][1] * i0);
            *reinterpret_cast<float2*>(&sO[r1 * 68 + h]) =
                make_float2(oacc[t][2] * i1, oacc[t][3] * i1);
        }
        __syncthreads();
        #pragma unroll
        for (int it = 0; it < 2; it++) {
            int idx = tid + it * 512;
            int row = idx >> 4, c4 = idx & 15;
            float4 t = *reinterpret_cast<const float4*>(&sO[row * 68 + 4 * c4]);
            *reinterpret_cast<float4*>(out + ((size_t)(n0 + row) * BB + b) * HH + 4 * c4) = t;
        }
    }
}

// ---------------------------------------------------------------------------
// Stream pool created at static init (host-side objects only; no device mem).
// ---------------------------------------------------------------------------
#define NGROUPS 4
struct Orch {
    cudaStream_t s[NGROUPS];
    cudaEvent_t  e0;
    cudaEvent_t  pe[NGROUPS];   // proj-done per group (serializes proj chain)
    cudaEvent_t  ae[NGROUPS];   // attn-done per group (join)
    Orch() {
        for (int i = 0; i < NGROUPS; i++)
            cudaStreamCreateWithFlags(&s[i], cudaStreamNonBlocking);
        cudaEventCreateWithFlags(&e0, cudaEventDisableTiming);
        for (int i = 0; i < NGROUPS; i++) {
            cudaEventCreateWithFlags(&pe[i], cudaEventDisableTiming);
            cudaEventCreateWithFlags(&ae[i], cudaEventDisableTiming);
        }
    }
};
static Orch g_orch;

extern "C" void kernel_launch(void* const* d_in, const int* in_sizes, int n_in,
                              void* d_out, int out_size)
{
    const float* q    = (const float*)d_in[0];
    const float* k    = (const float*)d_in[1];
    const float* v    = (const float*)d_in[2];
    const float* mask = (const float*)d_in[3];
    const float* Wq   = (const float*)d_in[4];
    const float* bq   = (const float*)d_in[5];
    const float* Wk   = (const float*)d_in[6];
    const float* bk   = (const float*)d_in[7];
    const float* Wv   = (const float*)d_in[8];
    const float* bv   = (const float*)d_in[9];

    float* out  = (float*)d_out;                         // [N,B,H] first
    float* Aout = (float*)d_out + (size_t)NN * BB * HH;  // then [B,N,N]

    const int smem_bytes = SMEM_FLOATS * 4;
    cudaFuncSetAttribute(attn_kernel, cudaFuncAttributeMaxDynamicSharedMemorySize,
                         smem_bytes);

    const int BPG = BB / NGROUPS;    // batches per group (32)

    // fork; proj chain serialized so group 0's proj finishes first and its
    // attn starts while later projs run underneath.
    cudaEventRecord(g_orch.e0, (cudaStream_t)0);
    for (int g = 0; g < NGROUPS; g++) {
        cudaStreamWaitEvent(g_orch.s[g], g_orch.e0, 0);
        if (g > 0) cudaStreamWaitEvent(g_orch.s[g], g_orch.pe[g - 1], 0);
        proj_kernel<<<dim3(BPG, 3), 256, 0, g_orch.s[g]>>>(
            g * BPG, q, k, v, Wq, bq, Wk, bk, Wv, bv);
        cudaEventRecord(g_orch.pe[g], g_orch.s[g]);
        attn_kernel<<<dim3(NN / 64, BPG), 512, smem_bytes, g_orch.s[g]>>>(
            g * BPG, mask, out, Aout);
        cudaEventRecord(g_orch.ae[g], g_orch.s[g]);
    }
    // join
    for (int g = 0; g < NGROUPS; g++)
        cudaStreamWaitEvent((cudaStream_t)0, g_orch.ae[g], 0);
}

// round 15
// speedup vs baseline: 1.0577x; 1.0314x over previous
#include <cuda_runtime.h>
#include <cstdint>

#define HH 64
#define NN 512
#define BB 128

__device__ float g_kp[BB * NN * HH];
__device__ float g_vp[BB * NN * HH];

// ---------------- helpers ----------------
__device__ __forceinline__ uint32_t tf32r(float f) {
    uint32_t u;
    asm("cvt.rna.tf32.f32 %0, %1;" : "=r"(u) : "f"(f));
    return u;
}
__device__ __forceinline__ void mma_tf32(float* d, const uint32_t* a,
                                         uint32_t b0, uint32_t b1) {
    asm volatile(
        "mma.sync.aligned.m16n8k8.row.col.f32.tf32.tf32.f32 "
        "{%0,%1,%2,%3}, {%4,%5,%6,%7}, {%8,%9}, {%0,%1,%2,%3};"
        : "+f"(d[0]), "+f"(d[1]), "+f"(d[2]), "+f"(d[3])
        : "r"(a[0]), "r"(a[1]), "r"(a[2]), "r"(a[3]), "r"(b0), "r"(b1));
}

// exp(s * 0.125) on FMA/ALU pipes only.
__device__ __forceinline__ float fexp8(float s) {
    float y = s * 0.18033688011112042f;      // 0.125 * log2(e)
    float z = y + 12582912.0f;               // RN to integer
    int   i = __float_as_int(z) - 0x4B400000;
    float f = y - (z - 12582912.0f);
    float p = 0.0013333558f;
    p = p * f + 0.0096181291f;
    p = p * f + 0.0555041087f;
    p = p * f + 0.2402265070f;
    p = p * f + 0.6931471806f;
    p = p * f + 1.0f;
    return __int_as_float(__float_as_int(p) + (i << 23));
}

// ---------------------------------------------------------------------------
// Projection for K and V only (Q is fused into attention).
// dst[b,n,h] = x[n,b,:] . W[h,:] + bias[h], stored tf32-pre-rounded.
// ---------------------------------------------------------------------------
__global__ __launch_bounds__(256, 2) void proj_kernel(
    const float* __restrict__ k, const float* __restrict__ v,
    const float* __restrict__ Wk, const float* __restrict__ bk,
    const float* __restrict__ Wv, const float* __restrict__ bv)
{
    __shared__ uint32_t sX[128 * 68];
    __shared__ uint32_t sW[64 * 68];
    __shared__ float    sB[64];

    const float* x; const float* W; const float* bias; float* dst;
    if (blockIdx.y == 0) { x = k; W = Wk; bias = bk; dst = g_kp; }
    else                 { x = v; W = Wv; bias = bv; dst = g_vp; }

    const int tid  = threadIdx.x;
    const int row0 = blockIdx.x * 128;

    #pragma unroll
    for (int it = 0; it < 8; it++) {
        int idx = tid + it * 256;
        int r = idx >> 4, c4 = idx & 15;
        float4 t = *reinterpret_cast<const float4*>(x + (size_t)(row0 + r) * HH + c4 * 4);
        uint4 u = { tf32r(t.x), tf32r(t.y), tf32r(t.z), tf32r(t.w) };
        *reinterpret_cast<uint4*>(&sX[r * 68 + c4 * 4]) = u;
    }
    #pragma unroll
    for (int it = 0; it < 4; it++) {
        int idx = tid + it * 256;
        int r = idx >> 4, c4 = idx & 15;
        float4 t = *reinterpret_cast<const float4*>(W + (size_t)r * HH + c4 * 4);
        uint4 u = { tf32r(t.x), tf32r(t.y), tf32r(t.z), tf32r(t.w) };
        *reinterpret_cast<uint4*>(&sW[r * 68 + c4 * 4]) = u;
    }
    if (tid < 64) sB[tid] = bias[tid];
    __syncthreads();

    const int w    = tid >> 5;
    const int lane = tid & 31;
    const int lx   = lane & 3;
    const int ly   = lane >> 2;
    const int r0   = w * 16 + ly;
    const int r1   = r0 + 8;

    float acc[8][4];
    #pragma unroll
    for (int t = 0; t < 8; t++)
        #pragma unroll
        for (int i = 0; i < 4; i++) acc[t][i] = 0.f;

    #pragma unroll
    for (int k0 = 0; k0 < 64; k0 += 8) {
        uint32_t a[4];
        a[0] = sX[r0 * 68 + k0 + lx];
        a[1] = sX[r1 * 68 + k0 + lx];
        a[2] = sX[r0 * 68 + k0 + lx + 4];
        a[3] = sX[r1 * 68 + k0 + lx + 4];
        #pragma unroll
        for (int t = 0; t < 8; t++) {
            uint32_t b0 = sW[(t * 8 + ly) * 68 + k0 + lx];
            uint32_t b1 = sW[(t * 8 + ly) * 68 + k0 + 4 + lx];
            mma_tf32(acc[t], a, b0, b1);
        }
    }

    int g0 = row0 + r0, g1 = row0 + r1;
    float* orow0 = dst + ((size_t)(g0 & 127) * NN + (g0 >> 7)) * HH;
    float* orow1 = dst + ((size_t)(g1 & 127) * NN + (g1 >> 7)) * HH;
    #pragma unroll
    for (int t = 0; t < 8; t++) {
        int c0 = t * 8 + 2 * lx;
        float b0 = sB[c0], b1 = sB[c0 + 1];
        float2 o0 = make_float2(__uint_as_float(tf32r(acc[t][0] + b0)),
                                __uint_as_float(tf32r(acc[t][1] + b1)));
        float2 o1 = make_float2(__uint_as_float(tf32r(acc[t][2] + b0)),
                                __uint_as_float(tf32r(acc[t][3] + b1)));
        *reinterpret_cast<float2*>(orow0 + c0) = o0;
        *reinterpret_cast<float2*>(orow1 + c0) = o1;
    }
}

// ---------------------------------------------------------------------------
// Attention (R8 structure) with fused Q-projection in the prologue.
// CTA = 64 n-rows x one batch, 512 threads (16 warps = 4 row-stripes x
// 4 col-quads), 4 chunks of 128 keys, e-tile in smem.
// ---------------------------------------------------------------------------
// smem float offsets
#define OQ   0                      // 64 x 68
#define OK_  4352                   // 128 x 68
#define OV   13056                  // 128 x 72
#define OA   22272                  // 64 x 516
#define OS   55296                  // 256 partial row sums (also bias stage)
#define OI   55552                  // 64 inverse sums
#define SMEM_FLOATS 55616

__global__ __launch_bounds__(512, 1) void attn_kernel(
    const float* __restrict__ q,     // raw q [N,B,H]
    const float* __restrict__ Wq, const float* __restrict__ bq,
    const float* __restrict__ mask,
    float* __restrict__ out,     // [N,B,H]
    float* __restrict__ Aout)    // [B,N,N]
{
    extern __shared__ float sm[];
    float*    sAf = sm + OA;
    uint32_t* sQu = reinterpret_cast<uint32_t*>(sm + OQ);
    uint32_t* sKu = reinterpret_cast<uint32_t*>(sm + OK_);
    uint32_t* sVu = reinterpret_cast<uint32_t*>(sm + OV);
    uint32_t* sAu = reinterpret_cast<uint32_t*>(sm + OA);

    const int tid  = threadIdx.x;
    const int w    = tid >> 5;
    const int lane = tid & 31;
    const int lx   = lane & 3;
    const int ly   = lane >> 2;
    const int stripe = w & 3;
    const int quad   = w >> 2;
    const int r0 = stripe * 16 + ly, r1 = r0 + 8;

    const int n0 = blockIdx.x * 64;
    const int b  = blockIdx.y;

    const float* kp = g_kp + (size_t)b * NN * HH;
    const float* vp = g_vp + (size_t)b * NN * HH;
    const float* mbase = mask + ((size_t)b * NN + n0) * NN;

    // ======== fused Q-projection prologue ========
    // Stage X = q rows n0..n0+63 of batch b into sK region (tf32-rounded);
    // Wq into sV region; bias into OS region.
    #pragma unroll
    for (int it = 0; it < 2; it++) {
        int idx = tid + it * 512;
        int r = idx >> 4, c4 = idx & 15;
        float4 t = *reinterpret_cast<const float4*>(
            q + ((size_t)(n0 + r) * BB + b) * HH + c4 * 4);
        uint4 u = { tf32r(t.x), tf32r(t.y), tf32r(t.z), tf32r(t.w) };
        *reinterpret_cast<uint4*>(&sKu[r * 68 + c4 * 4]) = u;
    }
    #pragma unroll
    for (int it = 0; it < 2; it++) {
        int idx = tid + it * 512;
        int r = idx >> 4, c4 = idx & 15;
        float4 t = *reinterpret_cast<const float4*>(Wq + (size_t)r * HH + c4 * 4);
        uint4 u = { tf32r(t.x), tf32r(t.y), tf32r(t.z), tf32r(t.w) };
        *reinterpret_cast<uint4*>(&sVu[r * 68 + c4 * 4]) = u;
    }
    if (tid < 64) sm[OS + tid] = bq[tid];
    __syncthreads();

    // Q-proj: warp (stripe, quad) computes rows r0/r1, cols quad*16..+15.
    {
        float qacc[2][4];
        #pragma unroll
        for (int t = 0; t < 2; t++)
            #pragma unroll
            for (int i = 0; i < 4; i++) qacc[t][i] = 0.f;
        #pragma unroll
        for (int kk = 0; kk < 8; kk++) {
            int k0 = kk * 8;
            uint32_t a[4];
            a[0] = sKu[r0 * 68 + k0 + lx];
            a[1] = sKu[r1 * 68 + k0 + lx];
            a[2] = sKu[r0 * 68 + k0 + lx + 4];
            a[3] = sKu[r1 * 68 + k0 + lx + 4];
            #pragma unroll
            for (int t = 0; t < 2; t++) {
                int col = quad * 16 + t * 8 + ly;
                uint32_t b0 = sVu[col * 68 + k0 + lx];
                uint32_t b1 = sVu[col * 68 + k0 + 4 + lx];
                mma_tf32(qacc[t], a, b0, b1);
            }
        }
        #pragma unroll
        for (int t = 0; t < 2; t++) {
            int c0 = quad * 16 + t * 8 + 2 * lx;
            float bb0 = sm[OS + c0], bb1 = sm[OS + c0 + 1];
            sQu[r0 * 68 + c0]     = tf32r(qacc[t][0] + bb0);
            sQu[r0 * 68 + c0 + 1] = tf32r(qacc[t][1] + bb1);
            sQu[r1 * 68 + c0]     = tf32r(qacc[t][2] + bb0);
            sQu[r1 * 68 + c0 + 1] = tf32r(qacc[t][3] + bb1);
        }
    }
    __syncthreads();

    // ---- Q fragments hoisted
    uint32_t qf[8][4];
    #pragma unroll
    for (int kk = 0; kk < 8; kk++) {
        int k0 = kk * 8;
        qf[kk][0] = sQu[r0 * 68 + k0 + lx];
        qf[kk][1] = sQu[r1 * 68 + k0 + lx];
        qf[kk][2] = sQu[r0 * 68 + k0 + lx + 4];
        qf[kk][3] = sQu[r1 * 68 + k0 + lx + 4];
    }

    float oacc[2][4];
    #pragma unroll
    for (int t = 0; t < 2; t++)
        #pragma unroll
        for (int i = 0; i < 4; i++) oacc[t][i] = 0.f;
    float rsum0 = 0.f, rsum1 = 0.f;

    for (int c = 0; c < 4; c++) {
        const int mt = c * 128;
        __syncthreads();

        #pragma unroll
        for (int it = 0; it < 4; it++) {
            int idx = tid + it * 512;
            int r = idx >> 4, c4 = idx & 15;
            float4 t = *reinterpret_cast<const float4*>(kp + (size_t)(mt + r) * HH + c4 * 4);
            *reinterpret_cast<float4*>(&sm[OK_ + r * 68 + c4 * 4]) = t;
            float4 s = *reinterpret_cast<const float4*>(vp + (size_t)(mt + r) * HH + c4 * 4);
            *reinterpret_cast<float4*>(&sm[OV + r * 72 + c4 * 4]) = s;
        }
        __syncthreads();

        float2 m0[4], m1[4];
        #pragma unroll
        for (int t = 0; t < 4; t++) {
            int gc = mt + quad * 32 + t * 8 + 2 * lx;
            m0[t] = *reinterpret_cast<const float2*>(mbase + (size_t)r0 * NN + gc);
            m1[t] = *reinterpret_cast<const float2*>(mbase + (size_t)r1 * NN + gc);
        }

        float sacc[4][4];
        #pragma unroll
        for (int t = 0; t < 4; t++)
            #pragma unroll
            for (int i = 0; i < 4; i++) sacc[t][i] = 0.f;

        #pragma unroll
        for (int kk = 0; kk < 8; kk++) {
            int k0 = kk * 8;
            #pragma unroll
            for (int t = 0; t < 4; t++) {
                int key = quad * 32 + t * 8 + ly;
                uint32_t bk0 = sKu[key * 68 + k0 + lx];
                uint32_t bk1 = sKu[key * 68 + k0 + 4 + lx];
                mma_tf32(sacc[t], qf[kk], bk0, bk1);
            }
        }

        #pragma unroll
        for (int t = 0; t < 4; t++) {
            int gc = mt + quad * 32 + t * 8 + 2 * lx;
            float e00 = __uint_as_float(tf32r(fexp8(sacc[t][0]) * m0[t].x));
            float e01 = __uint_as_float(tf32r(fexp8(sacc[t][1]) * m0[t].y));
            float e10 = __uint_as_float(tf32r(fexp8(sacc[t][2]) * m1[t].x));
            float e11 = __uint_as_float(tf32r(fexp8(sacc[t][3]) * m1[t].y));
            rsum0 += e00 + e01;
            rsum1 += e10 + e11;
            *reinterpret_cast<float2*>(&sAf[r0 * 516 + gc]) = make_float2(e00, e01);
            *reinterpret_cast<float2*>(&sAf[r1 * 516 + gc]) = make_float2(e10, e11);
        }
        __syncthreads();

        #pragma unroll
        for (int k0 = 0; k0 < 128; k0 += 8) {
            uint32_t a[4];
            a[0] = sAu[r0 * 516 + mt + k0 + lx];
            a[1] = sAu[r1 * 516 + mt + k0 + lx];
            a[2] = sAu[r0 * 516 + mt + k0 + lx + 4];
            a[3] = sAu[r1 * 516 + mt + k0 + lx + 4];
            #pragma unroll
            for (int t = 0; t < 2; t++) {
                int h = quad * 16 + t * 8 + ly;
                uint32_t bv0 = sVu[(k0 + lx) * 72 + h];
                uint32_t bv1 = sVu[(k0 + 4 + lx) * 72 + h];
                mma_tf32(oacc[t], a, bv0, bv1);
            }
        }
    }

    rsum0 += __shfl_xor_sync(0xffffffff, rsum0, 1);
    rsum0 += __shfl_xor_sync(0xffffffff, rsum0, 2);
    rsum1 += __shfl_xor_sync(0xffffffff, rsum1, 1);
    rsum1 += __shfl_xor_sync(0xffffffff, rsum1, 2);
    if (lx == 0) {
        sm[OS + quad * 64 + r0] = rsum0;
        sm[OS + quad * 64 + r1] = rsum1;
    }
    __syncthreads();
    if (tid < 64) {
        float s = sm[OS + tid] + sm[OS + 64 + tid] + sm[OS + 128 + tid] + sm[OS + 192 + tid];
        sm[OI + tid] = (s == 0.f) ? 1.f : (1.f / s);
    }
    __syncthreads();

    {
        int row = tid >> 3, s8 = tid & 7;
        float inv = sm[OI + row];
        float4* grow = reinterpret_cast<float4*>(Aout + ((size_t)b * NN + n0 + row) * NN);
        #pragma unroll
        for (int i = 0; i < 16; i++) {
            int c4 = s8 + 8 * i;
            float4 t = *reinterpret_cast<const float4*>(&sAf[row * 516 + 4 * c4]);
            t.x *= inv; t.y *= inv; t.z *= inv; t.w *= inv;
            grow[c4] = t;
        }
    }

    {
        float* sO = sm + OK_;
        float i0 = sm[OI + r0], i1 = sm[OI + r1];
        #pragma unroll
        for (int t = 0; t < 2; t++) {
            int h = quad * 16 + t * 8 + 2 * lx;
            *reinterpret_cast<float2*>(&sO[r0 * 68 + h]) =
                make_float2(oacc[t][0] * i0, oacc[t][1] * i0);
            *reinterpret_cast<float2*>(&sO[r1 * 68 + h]) =
                make_float2(oacc[t][2] * i1, oacc[t][3] * i1);
        }
        __syncthreads();
        #pragma unroll
        for (int it = 0; it < 2; it++) {
            int idx = tid + it * 512;
            int row = idx >> 4, c4 = idx & 15;
            float4 t = *reinterpret_cast<const float4*>(&sO[row * 68 + 4 * c4]);
            *reinterpret_cast<float4*>(out + ((size_t)(n0 + row) * BB + b) * HH + 4 * c4) = t;
        }
    }
}

// ---------------------------------------------------------------------------
extern "C" void kernel_launch(void* const* d_in, const int* in_sizes, int n_in,
                              void* d_out, int out_size)
{
    const float* q    = (const float*)d_in[0];
    const float* k    = (const float*)d_in[1];
    const float* v    = (const float*)d_in[2];
    const float* mask = (const float*)d_in[3];
    const float* Wq   = (const float*)d_in[4];
    const float* bq   = (const float*)d_in[5];
    const float* Wk   = (const float*)d_in[6];
    const float* bk   = (const float*)d_in[7];
    const float* Wv   = (const float*)d_in[8];
    const float* bv   = (const float*)d_in[9];

    float* out  = (float*)d_out;                         // [N,B,H] first
    float* Aout = (float*)d_out + (size_t)NN * BB * HH;  // then [B,N,N]

    const int smem_bytes = SMEM_FLOATS * 4;
    cudaFuncSetAttribute(attn_kernel, cudaFuncAttributeMaxDynamicSharedMemorySize,
                         smem_bytes);

    proj_kernel<<<dim3((NN * BB) / 128, 2), 256>>>(k, v, Wk, bk, Wv, bv);
    attn_kernel<<<dim3(NN / 64, BB), 512, smem_bytes>>>(q, Wq, bq, mask, out, Aout);
}

// round 16
// speedup vs baseline: 1.0825x; 1.0234x over previous
#include <cuda_runtime.h>
#include <cstdint>

#define HH 64
#define NN 512
#define BB 128

__device__ float g_kp[BB * NN * HH];
__device__ float g_vp[BB * NN * HH];

// ---------------- helpers ----------------
__device__ __forceinline__ uint32_t tf32r(float f) {
    uint32_t u;
    asm("cvt.rna.tf32.f32 %0, %1;" : "=r"(u) : "f"(f));
    return u;
}
__device__ __forceinline__ void mma_tf32(float* d, const uint32_t* a,
                                         uint32_t b0, uint32_t b1) {
    asm volatile(
        "mma.sync.aligned.m16n8k8.row.col.f32.tf32.tf32.f32 "
        "{%0,%1,%2,%3}, {%4,%5,%6,%7}, {%8,%9}, {%0,%1,%2,%3};"
        : "+f"(d[0]), "+f"(d[1]), "+f"(d[2]), "+f"(d[3])
        : "r"(a[0]), "r"(a[1]), "r"(a[2]), "r"(a[3]), "r"(b0), "r"(b1));
}
__device__ __forceinline__ void cpa16(uint32_t saddr, const void* gptr) {
    asm volatile("cp.async.cg.shared.global [%0], [%1], 16;" :: "r"(saddr), "l"(gptr));
}
__device__ __forceinline__ void cpa_commit() {
    asm volatile("cp.async.commit_group;" ::: "memory");
}
__device__ __forceinline__ void cpa_wait0() {
    asm volatile("cp.async.wait_group 0;" ::: "memory");
}

// exp(s * 0.125) on FMA/ALU pipes only.
__device__ __forceinline__ float fexp8(float s) {
    float y = s * 0.18033688011112042f;      // 0.125 * log2(e)
    float z = y + 12582912.0f;               // RN to integer
    int   i = __float_as_int(z) - 0x4B400000;
    float f = y - (z - 12582912.0f);
    float p = 0.0013333558f;
    p = p * f + 0.0096181291f;
    p = p * f + 0.0555041087f;
    p = p * f + 0.2402265070f;
    p = p * f + 0.6931471806f;
    p = p * f + 1.0f;
    return __int_as_float(__float_as_int(p) + (i << 23));
}

// ---------------------------------------------------------------------------
// Projection for K and V only (Q fused into attention).
// dst[b,n,h] = x[n,b,:] . W[h,:] + bias[h], stored tf32-pre-rounded.
// ---------------------------------------------------------------------------
__global__ __launch_bounds__(256, 2) void proj_kernel(
    const float* __restrict__ k, const float* __restrict__ v,
    const float* __restrict__ Wk, const float* __restrict__ bk,
    const float* __restrict__ Wv, const float* __restrict__ bv)
{
    __shared__ uint32_t sX[128 * 68];
    __shared__ uint32_t sW[64 * 68];
    __shared__ float    sB[64];

    const float* x; const float* W; const float* bias; float* dst;
    if (blockIdx.y == 0) { x = k; W = Wk; bias = bk; dst = g_kp; }
    else                 { x = v; W = Wv; bias = bv; dst = g_vp; }

    const int tid  = threadIdx.x;
    const int row0 = blockIdx.x * 128;

    #pragma unroll
    for (int it = 0; it < 8; it++) {
        int idx = tid + it * 256;
        int r = idx >> 4, c4 = idx & 15;
        float4 t = *reinterpret_cast<const float4*>(x + (size_t)(row0 + r) * HH + c4 * 4);
        uint4 u = { tf32r(t.x), tf32r(t.y), tf32r(t.z), tf32r(t.w) };
        *reinterpret_cast<uint4*>(&sX[r * 68 + c4 * 4]) = u;
    }
    #pragma unroll
    for (int it = 0; it < 4; it++) {
        int idx = tid + it * 256;
        int r = idx >> 4, c4 = idx & 15;
        float4 t = *reinterpret_cast<const float4*>(W + (size_t)r * HH + c4 * 4);
        uint4 u = { tf32r(t.x), tf32r(t.y), tf32r(t.z), tf32r(t.w) };
        *reinterpret_cast<uint4*>(&sW[r * 68 + c4 * 4]) = u;
    }
    if (tid < 64) sB[tid] = bias[tid];
    __syncthreads();

    const int w    = tid >> 5;
    const int lane = tid & 31;
    const int lx   = lane & 3;
    const int ly   = lane >> 2;
    const int r0   = w * 16 + ly;
    const int r1   = r0 + 8;

    float acc[8][4];
    #pragma unroll
    for (int t = 0; t < 8; t++)
        #pragma unroll
        for (int i = 0; i < 4; i++) acc[t][i] = 0.f;

    #pragma unroll
    for (int k0 = 0; k0 < 64; k0 += 8) {
        uint32_t a[4];
        a[0] = sX[r0 * 68 + k0 + lx];
        a[1] = sX[r1 * 68 + k0 + lx];
        a[2] = sX[r0 * 68 + k0 + lx + 4];
        a[3] = sX[r1 * 68 + k0 + lx + 4];
        #pragma unroll
        for (int t = 0; t < 8; t++) {
            uint32_t b0 = sW[(t * 8 + ly) * 68 + k0 + lx];
            uint32_t b1 = sW[(t * 8 + ly) * 68 + k0 + 4 + lx];
            mma_tf32(acc[t], a, b0, b1);
        }
    }

    int g0 = row0 + r0, g1 = row0 + r1;
    float* orow0 = dst + ((size_t)(g0 & 127) * NN + (g0 >> 7)) * HH;
    float* orow1 = dst + ((size_t)(g1 & 127) * NN + (g1 >> 7)) * HH;
    #pragma unroll
    for (int t = 0; t < 8; t++) {
        int c0 = t * 8 + 2 * lx;
        float b0 = sB[c0], b1 = sB[c0 + 1];
        float2 o0 = make_float2(__uint_as_float(tf32r(acc[t][0] + b0)),
                                __uint_as_float(tf32r(acc[t][1] + b1)));
        float2 o1 = make_float2(__uint_as_float(tf32r(acc[t][2] + b0)),
                                __uint_as_float(tf32r(acc[t][3] + b1)));
        *reinterpret_cast<float2*>(orow0 + c0) = o0;
        *reinterpret_cast<float2*>(orow1 + c0) = o1;
    }
}

// ---------------------------------------------------------------------------
// Attention with fused Q-projection hidden under chunk-0 cp.async K/V load.
// CTA = 64 n-rows x one batch, 512 threads (16 warps = 4 row-stripes x
// 4 col-quads), 4 chunks of 128 keys, e-tile in smem.
// ---------------------------------------------------------------------------
// smem float offsets
#define OQ   0                      // 64 x 68
#define OK_  4352                   // 128 x 68
#define OV   13056                  // 128 x 72
#define OA   22272                  // 64 x 516 (prologue: X stage @OA, Wq @OA+4352)
#define OS   55296                  // 256 partial row sums (also bias stage)
#define OI   55552                  // 64 inverse sums
#define SMEM_FLOATS 55616

__global__ __launch_bounds__(512, 1) void attn_kernel(
    const float* __restrict__ q,     // raw q [N,B,H]
    const float* __restrict__ Wq, const float* __restrict__ bq,
    const float* __restrict__ mask,
    float* __restrict__ out,     // [N,B,H]
    float* __restrict__ Aout)    // [B,N,N]
{
    extern __shared__ float sm[];
    float*    sAf = sm + OA;
    uint32_t* sQu = reinterpret_cast<uint32_t*>(sm + OQ);
    uint32_t* sKu = reinterpret_cast<uint32_t*>(sm + OK_);
    uint32_t* sVu = reinterpret_cast<uint32_t*>(sm + OV);
    uint32_t* sAu = reinterpret_cast<uint32_t*>(sm + OA);
    uint32_t* sXu = reinterpret_cast<uint32_t*>(sm + OA);          // prologue X stage
    uint32_t* sWu = reinterpret_cast<uint32_t*>(sm + OA + 4352);   // prologue Wq stage
    const uint32_t sbase = (uint32_t)__cvta_generic_to_shared(sm);

    const int tid  = threadIdx.x;
    const int w    = tid >> 5;
    const int lane = tid & 31;
    const int lx   = lane & 3;
    const int ly   = lane >> 2;
    const int stripe = w & 3;
    const int quad   = w >> 2;
    const int r0 = stripe * 16 + ly, r1 = r0 + 8;

    const int n0 = blockIdx.x * 64;
    const int b  = blockIdx.y;

    const float* kp = g_kp + (size_t)b * NN * HH;
    const float* vp = g_vp + (size_t)b * NN * HH;
    const float* mbase = mask + ((size_t)b * NN + n0) * NN;

    // ---- issue chunk-0 K/V via cp.async (fills sK/sV under the prologue)
    #pragma unroll
    for (int it = 0; it < 4; it++) {
        int idx = tid + it * 512;
        int r = idx >> 4, c4 = idx & 15;
        cpa16(sbase + (OK_ + r * 68 + c4 * 4) * 4, kp + (size_t)r * HH + c4 * 4);
        cpa16(sbase + (OV + r * 72 + c4 * 4) * 4, vp + (size_t)r * HH + c4 * 4);
    }
    cpa_commit();

    // ---- stage X (q rows n0..n0+63) and Wq into the (dead) sA region
    #pragma unroll
    for (int it = 0; it < 2; it++) {
        int idx = tid + it * 512;
        int r = idx >> 4, c4 = idx & 15;
        float4 t = *reinterpret_cast<const float4*>(
            q + ((size_t)(n0 + r) * BB + b) * HH + c4 * 4);
        uint4 u = { tf32r(t.x), tf32r(t.y), tf32r(t.z), tf32r(t.w) };
        *reinterpret_cast<uint4*>(&sXu[r * 68 + c4 * 4]) = u;
    }
    #pragma unroll
    for (int it = 0; it < 2; it++) {
        int idx = tid + it * 512;
        int r = idx >> 4, c4 = idx & 15;
        float4 t = *reinterpret_cast<const float4*>(Wq + (size_t)r * HH + c4 * 4);
        uint4 u = { tf32r(t.x), tf32r(t.y), tf32r(t.z), tf32r(t.w) };
        *reinterpret_cast<uint4*>(&sWu[r * 68 + c4 * 4]) = u;
    }
    if (tid < 64) sm[OS + tid] = bq[tid];
    __syncthreads();

    // ---- Q-proj: warp (stripe, quad) computes rows r0/r1, cols quad*16..+15
    {
        float qacc[2][4];
        #pragma unroll
        for (int t = 0; t < 2; t++)
            #pragma unroll
            for (int i = 0; i < 4; i++) qacc[t][i] = 0.f;
        #pragma unroll
        for (int kk = 0; kk < 8; kk++) {
            int k0 = kk * 8;
            uint32_t a[4];
            a[0] = sXu[r0 * 68 + k0 + lx];
            a[1] = sXu[r1 * 68 + k0 + lx];
            a[2] = sXu[r0 * 68 + k0 + lx + 4];
            a[3] = sXu[r1 * 68 + k0 + lx + 4];
            #pragma unroll
            for (int t = 0; t < 2; t++) {
                int col = quad * 16 + t * 8 + ly;
                uint32_t b0 = sWu[col * 68 + k0 + lx];
                uint32_t b1 = sWu[col * 68 + k0 + 4 + lx];
                mma_tf32(qacc[t], a, b0, b1);
            }
        }
        #pragma unroll
        for (int t = 0; t < 2; t++) {
            int c0 = quad * 16 + t * 8 + 2 * lx;
            float bb0 = sm[OS + c0], bb1 = sm[OS + c0 + 1];
            sQu[r0 * 68 + c0]     = tf32r(qacc[t][0] + bb0);
            sQu[r0 * 68 + c0 + 1] = tf32r(qacc[t][1] + bb1);
            sQu[r1 * 68 + c0]     = tf32r(qacc[t][2] + bb0);
            sQu[r1 * 68 + c0 + 1] = tf32r(qacc[t][3] + bb1);
        }
    }
    cpa_wait0();
    __syncthreads();   // sQ visible + chunk-0 K/V landed

    // ---- Q fragments hoisted
    uint32_t qf[8][4];
    #pragma unroll
    for (int kk = 0; kk < 8; kk++) {
        int k0 = kk * 8;
        qf[kk][0] = sQu[r0 * 68 + k0 + lx];
        qf[kk][1] = sQu[r1 * 68 + k0 + lx];
        qf[kk][2] = sQu[r0 * 68 + k0 + lx + 4];
        qf[kk][3] = sQu[r1 * 68 + k0 + lx + 4];
    }

    float oacc[2][4];
    #pragma unroll
    for (int t = 0; t < 2; t++)
        #pragma unroll
        for (int i = 0; i < 4; i++) oacc[t][i] = 0.f;
    float rsum0 = 0.f, rsum1 = 0.f;

    for (int c = 0; c < 4; c++) {
        const int mt = c * 128;
        if (c > 0) {
            __syncthreads();   // prev AV done with sK/sV
            #pragma unroll
            for (int it = 0; it < 4; it++) {
                int idx = tid + it * 512;
                int r = idx >> 4, c4 = idx & 15;
                float4 t = *reinterpret_cast<const float4*>(kp + (size_t)(mt + r) * HH + c4 * 4);
                *reinterpret_cast<float4*>(&sm[OK_ + r * 68 + c4 * 4]) = t;
                float4 s = *reinterpret_cast<const float4*>(vp + (size_t)(mt + r) * HH + c4 * 4);
                *reinterpret_cast<float4*>(&sm[OV + r * 72 + c4 * 4]) = s;
            }
            __syncthreads();
        }

        float2 m0[4], m1[4];
        #pragma unroll
        for (int t = 0; t < 4; t++) {
            int gc = mt + quad * 32 + t * 8 + 2 * lx;
            m0[t] = *reinterpret_cast<const float2*>(mbase + (size_t)r0 * NN + gc);
            m1[t] = *reinterpret_cast<const float2*>(mbase + (size_t)r1 * NN + gc);
        }

        float sacc[4][4];
        #pragma unroll
        for (int t = 0; t < 4; t++)
            #pragma unroll
            for (int i = 0; i < 4; i++) sacc[t][i] = 0.f;

        #pragma unroll
        for (int kk = 0; kk < 8; kk++) {
            int k0 = kk * 8;
            #pragma unroll
            for (int t = 0; t < 4; t++) {
                int key = quad * 32 + t * 8 + ly;
                uint32_t bk0 = sKu[key * 68 + k0 + lx];
                uint32_t bk1 = sKu[key * 68 + k0 + 4 + lx];
                mma_tf32(sacc[t], qf[kk], bk0, bk1);
            }
        }

        #pragma unroll
        for (int t = 0; t < 4; t++) {
            int gc = mt + quad * 32 + t * 8 + 2 * lx;
            float e00 = __uint_as_float(tf32r(fexp8(sacc[t][0]) * m0[t].x));
            float e01 = __uint_as_float(tf32r(fexp8(sacc[t][1]) * m0[t].y));
            float e10 = __uint_as_float(tf32r(fexp8(sacc[t][2]) * m1[t].x));
            float e11 = __uint_as_float(tf32r(fexp8(sacc[t][3]) * m1[t].y));
            rsum0 += e00 + e01;
            rsum1 += e10 + e11;
            *reinterpret_cast<float2*>(&sAf[r0 * 516 + gc]) = make_float2(e00, e01);
            *reinterpret_cast<float2*>(&sAf[r1 * 516 + gc]) = make_float2(e10, e11);
        }
        __syncthreads();

        #pragma unroll
        for (int k0 = 0; k0 < 128; k0 += 8) {
            uint32_t a[4];
            a[0] = sAu[r0 * 516 + mt + k0 + lx];
            a[1] = sAu[r1 * 516 + mt + k0 + lx];
            a[2] = sAu[r0 * 516 + mt + k0 + lx + 4];
            a[3] = sAu[r1 * 516 + mt + k0 + lx + 4];
            #pragma unroll
            for (int t = 0; t < 2; t++) {
                int h = quad * 16 + t * 8 + ly;
                uint32_t bv0 = sVu[(k0 + lx) * 72 + h];
                uint32_t bv1 = sVu[(k0 + 4 + lx) * 72 + h];
                mma_tf32(oacc[t], a, bv0, bv1);
            }
        }
    }

    rsum0 += __shfl_xor_sync(0xffffffff, rsum0, 1);
    rsum0 += __shfl_xor_sync(0xffffffff, rsum0, 2);
    rsum1 += __shfl_xor_sync(0xffffffff, rsum1, 1);
    rsum1 += __shfl_xor_sync(0xffffffff, rsum1, 2);
    if (lx == 0) {
        sm[OS + quad * 64 + r0] = rsum0;
        sm[OS + quad * 64 + r1] = rsum1;
    }
    __syncthreads();
    if (tid < 64) {
        float s = sm[OS + tid] + sm[OS + 64 + tid] + sm[OS + 128 + tid] + sm[OS + 192 + tid];
        sm[OI + tid] = (s == 0.f) ? 1.f : (1.f / s);
    }
    __syncthreads();

    {
        int row = tid >> 3, s8 = tid & 7;
        float inv = sm[OI + row];
        float4* grow = reinterpret_cast<float4*>(Aout + ((size_t)b * NN + n0 + row) * NN);
        #pragma unroll
        for (int i = 0; i < 16; i++) {
            int c4 = s8 + 8 * i;
            float4 t = *reinterpret_cast<const float4*>(&sAf[row * 516 + 4 * c4]);
            t.x *= inv; t.y *= inv; t.z *= inv; t.w *= inv;
            grow[c4] = t;
        }
    }

    {
        float* sO = sm + OK_;
        float i0 = sm[OI + r0], i1 = sm[OI + r1];
        #pragma unroll
        for (int t = 0; t < 2; t++) {
            int h = quad * 16 + t * 8 + 2 * lx;
            *reinterpret_cast<float2*>(&sO[r0 * 68 + h]) =
                make_float2(oacc[t][0] * i0, oacc[t][1] * i0);
            *reinterpret_cast<float2*>(&sO[r1 * 68 + h]) =
                make_float2(oacc[t][2] * i1, oacc[t][3] * i1);
        }
        __syncthreads();
        #pragma unroll
        for (int it = 0; it < 2; it++) {
            int idx = tid + it * 512;
            int row = idx >> 4, c4 = idx & 15;
            float4 t = *reinterpret_cast<const float4*>(&sO[row * 68 + 4 * c4]);
            *reinterpret_cast<float4*>(out + ((size_t)(n0 + row) * BB + b) * HH + 4 * c4) = t;
        }
    }
}

// ---------------------------------------------------------------------------
extern "C" void kernel_launch(void* const* d_in, const int* in_sizes, int n_in,
                              void* d_out, int out_size)
{
    const float* q    = (const float*)d_in[0];
    const float* k    = (const float*)d_in[1];
    const float* v    = (const float*)d_in[2];
    const float* mask = (const float*)d_in[3];
    const float* Wq   = (const float*)d_in[4];
    const float* bq   = (const float*)d_in[5];
    const float* Wk   = (const float*)d_in[6];
    const float* bk   = (const float*)d_in[7];
    const float* Wv   = (const float*)d_in[8];
    const float* bv   = (const float*)d_in[9];

    float* out  = (float*)d_out;                         // [N,B,H] first
    float* Aout = (float*)d_out + (size_t)NN * BB * HH;  // then [B,N,N]

    const int smem_bytes = SMEM_FLOATS * 4;
    cudaFuncSetAttribute(attn_kernel, cudaFuncAttributeMaxDynamicSharedMemorySize,
                         smem_bytes);

    proj_kernel<<<dim3((NN * BB) / 128, 2), 256>>>(k, v, Wk, bk, Wv, bv);
    attn_kernel<<<dim3(NN / 64, BB), 512, smem_bytes>>>(q, Wq, bq, mask, out, Aout);
}

// round 17
// speedup vs baseline: 1.1404x; 1.0535x over previous
#include <cuda_runtime.h>
#include <cstdint>

#define HH 64
#define NN 512
#define BB 128

__device__ float g_kp[BB * NN * HH];
__device__ float g_vp[BB * NN * HH];

// ---------------- helpers ----------------
__device__ __forceinline__ uint32_t tf32r(float f) {
    uint32_t u;
    asm("cvt.rna.tf32.f32 %0, %1;" : "=r"(u) : "f"(f));
    return u;
}
__device__ __forceinline__ void mma_tf32(float* d, const uint32_t* a,
                                         uint32_t b0, uint32_t b1) {
    asm volatile(
        "mma.sync.aligned.m16n8k8.row.col.f32.tf32.tf32.f32 "
        "{%0,%1,%2,%3}, {%4,%5,%6,%7}, {%8,%9}, {%0,%1,%2,%3};"
        : "+f"(d[0]), "+f"(d[1]), "+f"(d[2]), "+f"(d[3])
        : "r"(a[0]), "r"(a[1]), "r"(a[2]), "r"(a[3]), "r"(b0), "r"(b1));
}
__device__ __forceinline__ void cpa16(uint32_t saddr, const void* gptr) {
    asm volatile("cp.async.cg.shared.global [%0], [%1], 16;" :: "r"(saddr), "l"(gptr));
}
__device__ __forceinline__ void cpa_commit() {
    asm volatile("cp.async.commit_group;" ::: "memory");
}
__device__ __forceinline__ void cpa_wait0() {
    asm volatile("cp.async.wait_group 0;" ::: "memory");
}
__device__ __forceinline__ void cpa_wait1() {
    asm volatile("cp.async.wait_group 1;" ::: "memory");
}

// exp(s * 0.125) on FMA/ALU pipes only.
__device__ __forceinline__ float fexp8(float s) {
    float y = s * 0.18033688011112042f;      // 0.125 * log2(e)
    float z = y + 12582912.0f;               // RN to integer
    int   i = __float_as_int(z) - 0x4B400000;
    float f = y - (z - 12582912.0f);
    float p = 0.0013333558f;
    p = p * f + 0.0096181291f;
    p = p * f + 0.0555041087f;
    p = p * f + 0.2402265070f;
    p = p * f + 0.6931471806f;
    p = p * f + 1.0f;
    return __int_as_float(__float_as_int(p) + (i << 23));
}

// ---------------------------------------------------------------------------
// Projection for K and V only (Q fused into attention).
// dst[b,n,h] = x[n,b,:] . W[h,:] + bias[h], stored tf32-pre-rounded.
// ---------------------------------------------------------------------------
__global__ __launch_bounds__(256, 2) void proj_kernel(
    const float* __restrict__ k, const float* __restrict__ v,
    const float* __restrict__ Wk, const float* __restrict__ bk,
    const float* __restrict__ Wv, const float* __restrict__ bv)
{
    __shared__ uint32_t sX[128 * 68];
    __shared__ uint32_t sW[64 * 68];
    __shared__ float    sB[64];

    const float* x; const float* W; const float* bias; float* dst;
    if (blockIdx.y == 0) { x = k; W = Wk; bias = bk; dst = g_kp; }
    else                 { x = v; W = Wv; bias = bv; dst = g_vp; }

    const int tid  = threadIdx.x;
    const int row0 = blockIdx.x * 128;

    #pragma unroll
    for (int it = 0; it < 8; it++) {
        int idx = tid + it * 256;
        int r = idx >> 4, c4 = idx & 15;
        float4 t = *reinterpret_cast<const float4*>(x + (size_t)(row0 + r) * HH + c4 * 4);
        uint4 u = { tf32r(t.x), tf32r(t.y), tf32r(t.z), tf32r(t.w) };
        *reinterpret_cast<uint4*>(&sX[r * 68 + c4 * 4]) = u;
    }
    #pragma unroll
    for (int it = 0; it < 4; it++) {
        int idx = tid + it * 256;
        int r = idx >> 4, c4 = idx & 15;
        float4 t = *reinterpret_cast<const float4*>(W + (size_t)r * HH + c4 * 4);
        uint4 u = { tf32r(t.x), tf32r(t.y), tf32r(t.z), tf32r(t.w) };
        *reinterpret_cast<uint4*>(&sW[r * 68 + c4 * 4]) = u;
    }
    if (tid < 64) sB[tid] = bias[tid];
    __syncthreads();

    const int w    = tid >> 5;
    const int lane = tid & 31;
    const int lx   = lane & 3;
    const int ly   = lane >> 2;
    const int r0   = w * 16 + ly;
    const int r1   = r0 + 8;

    float acc[8][4];
    #pragma unroll
    for (int t = 0; t < 8; t++)
        #pragma unroll
        for (int i = 0; i < 4; i++) acc[t][i] = 0.f;

    #pragma unroll
    for (int k0 = 0; k0 < 64; k0 += 8) {
        uint32_t a[4];
        a[0] = sX[r0 * 68 + k0 + lx];
        a[1] = sX[r1 * 68 + k0 + lx];
        a[2] = sX[r0 * 68 + k0 + lx + 4];
        a[3] = sX[r1 * 68 + k0 + lx + 4];
        #pragma unroll
        for (int t = 0; t < 8; t++) {
            uint32_t b0 = sW[(t * 8 + ly) * 68 + k0 + lx];
            uint32_t b1 = sW[(t * 8 + ly) * 68 + k0 + 4 + lx];
            mma_tf32(acc[t], a, b0, b1);
        }
    }

    int g0 = row0 + r0, g1 = row0 + r1;
    float* orow0 = dst + ((size_t)(g0 & 127) * NN + (g0 >> 7)) * HH;
    float* orow1 = dst + ((size_t)(g1 & 127) * NN + (g1 >> 7)) * HH;
    #pragma unroll
    for (int t = 0; t < 8; t++) {
        int c0 = t * 8 + 2 * lx;
        float b0 = sB[c0], b1 = sB[c0 + 1];
        float2 o0 = make_float2(__uint_as_float(tf32r(acc[t][0] + b0)),
                                __uint_as_float(tf32r(acc[t][1] + b1)));
        float2 o1 = make_float2(__uint_as_float(tf32r(acc[t][2] + b0)),
                                __uint_as_float(tf32r(acc[t][3] + b1)));
        *reinterpret_cast<float2*>(orow0 + c0) = o0;
        *reinterpret_cast<float2*>(orow1 + c0) = o1;
    }
}

// ---------------------------------------------------------------------------
// Attention: fused Q-proj prologue + phase-shifted cp.async K/V pipeline.
// CTA = 64 n-rows x one batch, 512 threads (16 warps = 4 row-stripes x
// 4 col-quads), 4 chunks of 128 keys, e-tile in smem.
// K(c+1) issued after e-sync (lands under AV); V(c+1) issued after AV-sync
// (lands under next S). Top-of-loop waits K only (wait_group 1).
// ---------------------------------------------------------------------------
// smem float offsets
#define OQ   0                      // 64 x 68
#define OK_  4352                   // 128 x 68
#define OV   13056                  // 128 x 72
#define OA   22272                  // 64 x 516 (prologue: X stage @OA, Wq @OA+4352)
#define OS   55296                  // 256 partial row sums (also bias stage)
#define OI   55552                  // 64 inverse sums
#define SMEM_FLOATS 55616

__global__ __launch_bounds__(512, 1) void attn_kernel(
    const float* __restrict__ q,     // raw q [N,B,H]
    const float* __restrict__ Wq, const float* __restrict__ bq,
    const float* __restrict__ mask,
    float* __restrict__ out,     // [N,B,H]
    float* __restrict__ Aout)    // [B,N,N]
{
    extern __shared__ float sm[];
    float*    sAf = sm + OA;
    uint32_t* sQu = reinterpret_cast<uint32_t*>(sm + OQ);
    uint32_t* sKu = reinterpret_cast<uint32_t*>(sm + OK_);
    uint32_t* sVu = reinterpret_cast<uint32_t*>(sm + OV);
    uint32_t* sAu = reinterpret_cast<uint32_t*>(sm + OA);
    uint32_t* sXu = reinterpret_cast<uint32_t*>(sm + OA);          // prologue X stage
    uint32_t* sWu = reinterpret_cast<uint32_t*>(sm + OA + 4352);   // prologue Wq stage
    const uint32_t sbase = (uint32_t)__cvta_generic_to_shared(sm);

    const int tid  = threadIdx.x;
    const int w    = tid >> 5;
    const int lane = tid & 31;
    const int lx   = lane & 3;
    const int ly   = lane >> 2;
    const int stripe = w & 3;
    const int quad   = w >> 2;
    const int r0 = stripe * 16 + ly, r1 = r0 + 8;

    const int n0 = blockIdx.x * 64;
    const int b  = blockIdx.y;

    const float* kp = g_kp + (size_t)b * NN * HH;
    const float* vp = g_vp + (size_t)b * NN * HH;
    const float* mbase = mask + ((size_t)b * NN + n0) * NN;

    // ---- issue chunk-0 K then V via cp.async (two groups: K older, V newer)
    #pragma unroll
    for (int it = 0; it < 4; it++) {
        int idx = tid + it * 512;
        int r = idx >> 4, c4 = idx & 15;
        cpa16(sbase + (OK_ + r * 68 + c4 * 4) * 4, kp + (size_t)r * HH + c4 * 4);
    }
    cpa_commit();
    #pragma unroll
    for (int it = 0; it < 4; it++) {
        int idx = tid + it * 512;
        int r = idx >> 4, c4 = idx & 15;
        cpa16(sbase + (OV + r * 72 + c4 * 4) * 4, vp + (size_t)r * HH + c4 * 4);
    }
    cpa_commit();

    // ---- stage X (q rows n0..n0+63) and Wq into the (dead) sA region
    #pragma unroll
    for (int it = 0; it < 2; it++) {
        int idx = tid + it * 512;
        int r = idx >> 4, c4 = idx & 15;
        float4 t = *reinterpret_cast<const float4*>(
            q + ((size_t)(n0 + r) * BB + b) * HH + c4 * 4);
        uint4 u = { tf32r(t.x), tf32r(t.y), tf32r(t.z), tf32r(t.w) };
        *reinterpret_cast<uint4*>(&sXu[r * 68 + c4 * 4]) = u;
    }
    #pragma unroll
    for (int it = 0; it < 2; it++) {
        int idx = tid + it * 512;
        int r = idx >> 4, c4 = idx & 15;
        float4 t = *reinterpret_cast<const float4*>(Wq + (size_t)r * HH + c4 * 4);
        uint4 u = { tf32r(t.x), tf32r(t.y), tf32r(t.z), tf32r(t.w) };
        *reinterpret_cast<uint4*>(&sWu[r * 68 + c4 * 4]) = u;
    }
    if (tid < 64) sm[OS + tid] = bq[tid];
    __syncthreads();

    // ---- Q-proj: warp (stripe, quad) computes rows r0/r1, cols quad*16..+15
    {
        float qacc[2][4];
        #pragma unroll
        for (int t = 0; t < 2; t++)
            #pragma unroll
            for (int i = 0; i < 4; i++) qacc[t][i] = 0.f;
        #pragma unroll
        for (int kk = 0; kk < 8; kk++) {
            int k0 = kk * 8;
            uint32_t a[4];
            a[0] = sXu[r0 * 68 + k0 + lx];
            a[1] = sXu[r1 * 68 + k0 + lx];
            a[2] = sXu[r0 * 68 + k0 + lx + 4];
            a[3] = sXu[r1 * 68 + k0 + lx + 4];
            #pragma unroll
            for (int t = 0; t < 2; t++) {
                int col = quad * 16 + t * 8 + ly;
                uint32_t b0 = sWu[col * 68 + k0 + lx];
                uint32_t b1 = sWu[col * 68 + k0 + 4 + lx];
                mma_tf32(qacc[t], a, b0, b1);
            }
        }
        #pragma unroll
        for (int t = 0; t < 2; t++) {
            int c0 = quad * 16 + t * 8 + 2 * lx;
            float bb0 = sm[OS + c0], bb1 = sm[OS + c0 + 1];
            sQu[r0 * 68 + c0]     = tf32r(qacc[t][0] + bb0);
            sQu[r0 * 68 + c0 + 1] = tf32r(qacc[t][1] + bb1);
            sQu[r1 * 68 + c0]     = tf32r(qacc[t][2] + bb0);
            sQu[r1 * 68 + c0 + 1] = tf32r(qacc[t][3] + bb1);
        }
    }
    __syncthreads();   // sQ visible

    // ---- Q fragments hoisted
    uint32_t qf[8][4];
    #pragma unroll
    for (int kk = 0; kk < 8; kk++) {
        int k0 = kk * 8;
        qf[kk][0] = sQu[r0 * 68 + k0 + lx];
        qf[kk][1] = sQu[r1 * 68 + k0 + lx];
        qf[kk][2] = sQu[r0 * 68 + k0 + lx + 4];
        qf[kk][3] = sQu[r1 * 68 + k0 + lx + 4];
    }

    float oacc[2][4];
    #pragma unroll
    for (int t = 0; t < 2; t++)
        #pragma unroll
        for (int i = 0; i < 4; i++) oacc[t][i] = 0.f;
    float rsum0 = 0.f, rsum1 = 0.f;

    for (int c = 0; c < 4; c++) {
        const int mt = c * 128;

        cpa_wait1();       // K(c) complete (V(c) may still be in flight)
        __syncthreads();   // K visible CTA-wide; prev AV done with sA cols

        float2 m0[4], m1[4];
        #pragma unroll
        for (int t = 0; t < 4; t++) {
            int gc = mt + quad * 32 + t * 8 + 2 * lx;
            m0[t] = *reinterpret_cast<const float2*>(mbase + (size_t)r0 * NN + gc);
            m1[t] = *reinterpret_cast<const float2*>(mbase + (size_t)r1 * NN + gc);
        }

        float sacc[4][4];
        #pragma unroll
        for (int t = 0; t < 4; t++)
            #pragma unroll
            for (int i = 0; i < 4; i++) sacc[t][i] = 0.f;

        #pragma unroll
        for (int kk = 0; kk < 8; kk++) {
            int k0 = kk * 8;
            #pragma unroll
            for (int t = 0; t < 4; t++) {
                int key = quad * 32 + t * 8 + ly;
                uint32_t bk0 = sKu[key * 68 + k0 + lx];
                uint32_t bk1 = sKu[key * 68 + k0 + 4 + lx];
                mma_tf32(sacc[t], qf[kk], bk0, bk1);
            }
        }

        #pragma unroll
        for (int t = 0; t < 4; t++) {
            int gc = mt + quad * 32 + t * 8 + 2 * lx;
            float e00 = __uint_as_float(tf32r(fexp8(sacc[t][0]) * m0[t].x));
            float e01 = __uint_as_float(tf32r(fexp8(sacc[t][1]) * m0[t].y));
            float e10 = __uint_as_float(tf32r(fexp8(sacc[t][2]) * m1[t].x));
            float e11 = __uint_as_float(tf32r(fexp8(sacc[t][3]) * m1[t].y));
            rsum0 += e00 + e01;
            rsum1 += e10 + e11;
            *reinterpret_cast<float2*>(&sAf[r0 * 516 + gc]) = make_float2(e00, e01);
            *reinterpret_cast<float2*>(&sAf[r1 * 516 + gc]) = make_float2(e10, e11);
        }

        cpa_wait0();       // V(c) complete
        __syncthreads();   // e + V visible; sK dead

        // prefetch K(c+1) into sK — lands while AV(c) runs
        if (c < 3) {
            #pragma unroll
            for (int it = 0; it < 4; it++) {
                int idx = tid + it * 512;
                int r = idx >> 4, c4 = idx & 15;
                cpa16(sbase + (OK_ + r * 68 + c4 * 4) * 4,
                      kp + (size_t)(mt + 128 + r) * HH + c4 * 4);
            }
        }
        cpa_commit();

        #pragma unroll
        for (int k0 = 0; k0 < 128; k0 += 8) {
            uint32_t a[4];
            a[0] = sAu[r0 * 516 + mt + k0 + lx];
            a[1] = sAu[r1 * 516 + mt + k0 + lx];
            a[2] = sAu[r0 * 516 + mt + k0 + lx + 4];
            a[3] = sAu[r1 * 516 + mt + k0 + lx + 4];
            #pragma unroll
            for (int t = 0; t < 2; t++) {
                int h = quad * 16 + t * 8 + ly;
                uint32_t bv0 = sVu[(k0 + lx) * 72 + h];
                uint32_t bv1 = sVu[(k0 + 4 + lx) * 72 + h];
                mma_tf32(oacc[t], a, bv0, bv1);
            }
        }
        __syncthreads();   // sV dead

        // prefetch V(c+1) into sV — lands while S(c+1)+exp run
        if (c < 3) {
            #pragma unroll
            for (int it = 0; it < 4; it++) {
                int idx = tid + it * 512;
                int r = idx >> 4, c4 = idx & 15;
                cpa16(sbase + (OV + r * 72 + c4 * 4) * 4,
                      vp + (size_t)(mt + 128 + r) * HH + c4 * 4);
            }
        }
        cpa_commit();
    }

    rsum0 += __shfl_xor_sync(0xffffffff, rsum0, 1);
    rsum0 += __shfl_xor_sync(0xffffffff, rsum0, 2);
    rsum1 += __shfl_xor_sync(0xffffffff, rsum1, 1);
    rsum1 += __shfl_xor_sync(0xffffffff, rsum1, 2);
    if (lx == 0) {
        sm[OS + quad * 64 + r0] = rsum0;
        sm[OS + quad * 64 + r1] = rsum1;
    }
    __syncthreads();
    if (tid < 64) {
        float s = sm[OS + tid] + sm[OS + 64 + tid] + sm[OS + 128 + tid] + sm[OS + 192 + tid];
        sm[OI + tid] = (s == 0.f) ? 1.f : (1.f / s);
    }
    __syncthreads();

    {
        int row = tid >> 3, s8 = tid & 7;
        float inv = sm[OI + row];
        float4* grow = reinterpret_cast<float4*>(Aout + ((size_t)b * NN + n0 + row) * NN);
        #pragma unroll
        for (int i = 0; i < 16; i++) {
            int c4 = s8 + 8 * i;
            float4 t = *reinterpret_cast<const float4*>(&sAf[row * 516 + 4 * c4]);
            t.x *= inv; t.y *= inv; t.z *= inv; t.w *= inv;
            grow[c4] = t;
        }
    }

    {
        float* sO = sm + OK_;
        float i0 = sm[OI + r0], i1 = sm[OI + r1];
        #pragma unroll
        for (int t = 0; t < 2; t++) {
            int h = quad * 16 + t * 8 + 2 * lx;
            *reinterpret_cast<float2*>(&sO[r0 * 68 + h]) =
                make_float2(oacc[t][0] * i0, oacc[t][1] * i0);
            *reinterpret_cast<float2*>(&sO[r1 * 68 + h]) =
                make_float2(oacc[t][2] * i1, oacc[t][3] * i1);
        }
        __syncthreads();
        #pragma unroll
        for (int it = 0; it < 2; it++) {
            int idx = tid + it * 512;
            int row = idx >> 4, c4 = idx & 15;
            float4 t = *reinterpret_cast<const float4*>(&sO[row * 68 + 4 * c4]);
            *reinterpret_cast<float4*>(out + ((size_t)(n0 + row) * BB + b) * HH + 4 * c4) = t;
        }
    }
}

// ---------------------------------------------------------------------------
extern "C" void kernel_launch(void* const* d_in, const int* in_sizes, int n_in,
                              void* d_out, int out_size)
{
    const float* q    = (const float*)d_in[0];
    const float* k    = (const float*)d_in[1];
    const float* v    = (const float*)d_in[2];
    const float* mask = (const float*)d_in[3];
    const float* Wq   = (const float*)d_in[4];
    const float* bq   = (const float*)d_in[5];
    const float* Wk   = (const float*)d_in[6];
    const float* bk   = (const float*)d_in[7];
    const float* Wv   = (const float*)d_in[8];
    const float* bv   = (const float*)d_in[9];

    float* out  = (float*)d_out;                         // [N,B,H] first
    float* Aout = (float*)d_out + (size_t)NN * BB * HH;  // then [B,N,N]

    const int smem_bytes = SMEM_FLOATS * 4;
    cudaFuncSetAttribute(attn_kernel, cudaFuncAttributeMaxDynamicSharedMemorySize,
                         smem_bytes);

    proj_kernel<<<dim3((NN * BB) / 128, 2), 256>>>(k, v, Wk, bk, Wv, bv);
    attn_kernel<<<dim3(NN / 64, BB), 512, smem_bytes>>>(q, Wq, bq, mask, out, Aout);
}